// round 16
// baseline (speedup 1.0000x reference)
#include <cuda_runtime.h>
#include <cuda_fp16.h>
#include <mma.h>
#include <math.h>
#include <stdint.h>

using namespace nvcuda;

#define NL 4
#define DD 512
#define DII 1024
#define DSS 16
#define VV 50257
#define BB 2
#define SS 1024
#define BSS 2048    /* BB*SS */
#define NPADV 50432 /* VV padded to 128 */

// ---------------- scratch (static device globals; no allocations) ----------
__device__ __align__(256) float g_h[BSS * DD];
__device__ __align__(256) float g_proj[BSS * 2 * DII];
__device__ __align__(256) float g_xc[BSS * DII];
__device__ __align__(256) float g_coeff[BSS * 48];
__device__ __align__(256) float g_xnorm[BSS];
__device__ __align__(256) float g_part[4 * BSS * DD];   // out_pw split4 / xproj split8 partials
// fp16 hi/lo staging (split fused into producer kernels)
__device__ __align__(256) __half g_Hhi[BSS * DD];
__device__ __align__(256) __half g_Hlo[BSS * DD];
__device__ __align__(256) __half g_XChi[BSS * DII];
__device__ __align__(256) __half g_XClo[BSS * DII];
__device__ __align__(256) __half g_Yhi[BSS * DII];
__device__ __align__(256) __half g_Ylo[BSS * DII];
// per-weight fp16 buffers (all layers, split once per launch)
__device__ __align__(256) __half g_Wihi[NL * DD * 2 * DII];
__device__ __align__(256) __half g_Wilo[NL * DD * 2 * DII];
__device__ __align__(256) __half g_Wohi[NL * DII * DD];
__device__ __align__(256) __half g_Wolo[NL * DII * DD];
__device__ __align__(256) __half g_Wxhi[NL * DII * 128];
__device__ __align__(256) __half g_Wxlo[NL * DII * 128];
__device__ __align__(256) __half g_Bhi[NPADV * DD];     // logits weight (hi only)

// ---------------- helpers ---------------------------------------------------
__device__ __forceinline__ float warp_sum(float v) {
#pragma unroll
    for (int o = 16; o > 0; o >>= 1) v += __shfl_xor_sync(0xffffffffu, v, o);
    return v;
}
__device__ __forceinline__ float silu_f(float x) {
    return x * (1.0f / (1.0f + __expf(-x)));
}
__device__ __forceinline__ void split_f16(float x, __half& hi, __half& lo) {
    hi = __float2half_rn(x);
    lo = __float2half_rn(x - __half2float(hi));
}
__device__ __forceinline__ uint32_t smem_u32(const void* p) {
    uint32_t a;
    asm("{ .reg .u64 t; cvta.to.shared.u64 t, %1; cvt.u32.u64 %0, t; }" : "=r"(a) : "l"(p));
    return a;
}
__device__ __forceinline__ void cp_async16(uint32_t dst, const void* src) {
    asm volatile("cp.async.cg.shared.global [%0], [%1], 16;" :: "r"(dst), "l"(src));
}
__device__ __forceinline__ void cp_commit() {
    asm volatile("cp.async.commit_group;" ::: "memory");
}
template<int N> __device__ __forceinline__ void cp_wait() {
    asm volatile("cp.async.wait_group %0;" :: "n"(N) : "memory");
}

// ---------------- K0: embedding gather + pos (+ fp16 hi/lo) -----------------
__global__ void embed_kernel(const int* __restrict__ x, const float* __restrict__ emb,
                             const float* __restrict__ pos, float* __restrict__ h,
                             __half* __restrict__ hhi, __half* __restrict__ hlo) {
    int bs = blockIdx.x;
    int s  = bs & (SS - 1);
    int tok = x[bs];
    const float4* e4 = (const float4*)(emb + (size_t)tok * DD);
    const float4* p4 = (const float4*)(pos + (size_t)s * DD);
    int i = threadIdx.x;
    float4 a = e4[i], p = p4[i];
    float4 v = make_float4(a.x + p.x, a.y + p.y, a.z + p.z, a.w + p.w);
    size_t gi = (size_t)bs * (DD / 4) + i;
    ((float4*)h)[gi] = v;
    __half h0, l0, h1, l1, h2, l2, h3, l3;
    split_f16(v.x, h0, l0); split_f16(v.y, h1, l1);
    split_f16(v.z, h2, l2); split_f16(v.w, h3, l3);
    ((__half2*)hhi)[gi * 2]     = __halves2half2(h0, h1);
    ((__half2*)hhi)[gi * 2 + 1] = __halves2half2(h2, h3);
    ((__half2*)hlo)[gi * 2]     = __halves2half2(l0, l1);
    ((__half2*)hlo)[gi * 2 + 1] = __halves2half2(l2, l3);
}

// ---------------- prepass: fp32 B[K,N] -> fp16 hi(/lo) [K,NPAD] (padded) ----
// float4 fast path when row-aligned and in-bounds.
__global__ void splitB_kernel(const float* __restrict__ B,
                              __half* __restrict__ hi, __half* __restrict__ lo,
                              int K, int N, int NPAD) {
    int idx = blockIdx.x * 256 + threadIdx.x;        // per 4 outputs
    int k = idx / (NPAD >> 2);
    int n4 = (idx - k * (NPAD >> 2)) << 2;
    size_t src = (size_t)k * N + n4;
    float v0, v1, v2, v3;
    if ((n4 + 3 < N) && ((src & 3) == 0)) {
        float4 d = __ldg((const float4*)(B + src));
        v0 = d.x; v1 = d.y; v2 = d.z; v3 = d.w;
    } else {
        v0 = (n4     < N) ? __ldg(B + src)     : 0.0f;
        v1 = (n4 + 1 < N) ? __ldg(B + src + 1) : 0.0f;
        v2 = (n4 + 2 < N) ? __ldg(B + src + 2) : 0.0f;
        v3 = (n4 + 3 < N) ? __ldg(B + src + 3) : 0.0f;
    }
    __half h0, l0, h1, l1, h2, l2, h3, l3;
    split_f16(v0, h0, l0); split_f16(v1, h1, l1);
    split_f16(v2, h2, l2); split_f16(v3, h3, l3);
    size_t o = ((size_t)k * NPAD + n4) >> 1;
    ((__half2*)hi)[o]     = __halves2half2(h0, h1);
    ((__half2*)hi)[o + 1] = __halves2half2(h2, h3);
    if (lo) {
        ((__half2*)lo)[o]     = __halves2half2(l0, l1);
        ((__half2*)lo)[o + 1] = __halves2half2(l2, l3);
    }
}

// ---------------- GEMM: fp16 wmma, TERMS=3 (2-stage) or 1 (4-stage) ---------
// C[M,N] = (Ahi[+Alo])[M,lda] @ Bhi(+Blo)[*,ldb]; Kloop columns per z-part.
// gridDim.z = K-split parts; part z writes to C + z*M*N (mode 0 only).
// mode 0: plain, 1: +bias[n], 2: += addsrc[m,n]. M%128==0, Kloop%32==0, KT>=2.
// 2 CTAs/SM; 128x128 tile, 8 warps of 32x64.
#define ST3 37888
#define ST1 18944

template<int TERMS>
__global__ __launch_bounds__(256, 2)
void gemm_f16(const __half* __restrict__ Ahi, const __half* __restrict__ Alo,
              const __half* __restrict__ Bhi, const __half* __restrict__ Blo,
              float* __restrict__ C, int M, int N, int ldb, int lda, int Kloop,
              const float* __restrict__ bias, const float* __restrict__ addsrc,
              int mode) {
    constexpr int ABYTES = (TERMS >= 2) ? 20480 : 10240;
    constexpr int STAGE  = ABYTES + 8704 * ((TERMS == 3) ? 2 : 1);
    constexpr int NST    = (TERMS == 1) ? 4 : 2;
    extern __shared__ __align__(128) char dsm[];
    __shared__ __align__(128) float sC[8 * 16 * 20];

    const int tid = threadIdx.x;
    const int warpId = tid >> 5, lane = tid & 31;
    const int wm = warpId >> 1;        // 0..3 -> 32-row slab
    const int wn = warpId & 1;         // 0..1 -> 64-col slab
    const int bm = blockIdx.x * 128;
    const int bn = blockIdx.y * 128;
    const int koff = blockIdx.z * Kloop;
    const int KT = Kloop >> 5;
    const uint32_t sbase = smem_u32(dsm);
    if (blockIdx.z) C += (size_t)blockIdx.z * M * N;

    wmma::fragment<wmma::accumulator, 16, 16, 16, float> acc[2][4];
#pragma unroll
    for (int i = 0; i < 2; i++)
#pragma unroll
        for (int j = 0; j < 4; j++) wmma::fill_fragment(acc[i][j], 0.0f);

    auto load_tile = [&](int kt) {
        const uint32_t base = sbase + (uint32_t)(kt % NST) * STAGE;
        const int k0 = koff + (kt << 5);
#pragma unroll
        for (int i = 0; i < 2; i++) {
            int idx = i * 256 + tid;
            int row = idx >> 2, c = idx & 3;
            uint32_t off = (uint32_t)(row * 40 + c * 8) * 2;
            size_t go = (size_t)(bm + row) * lda + k0 + c * 8;
            cp_async16(base + off, Ahi + go);
            if (TERMS >= 2)
                cp_async16(base + 10240 + off, Alo + go);
        }
#pragma unroll
        for (int i = 0; i < 2; i++) {
            int idx = i * 256 + tid;
            int row = idx >> 4, c = idx & 15;
            uint32_t off = (uint32_t)(row * 136 + c * 8) * 2;
            size_t go = (size_t)(k0 + row) * ldb + bn + c * 8;
            cp_async16(base + ABYTES + off, Bhi + go);
            if (TERMS == 3)
                cp_async16(base + ABYTES + 8704 + off, Blo + go);
        }
        cp_commit();
    };

    load_tile(0);
    if (KT > 1) load_tile(1);
    if (NST >= 4 && KT > 2) load_tile(2);

    for (int kt = 0; kt < KT; kt++) {
        const int rem = KT - 1 - kt;   // tiles after this one
        if (NST == 4) {
            if (rem >= 2)      cp_wait<2>();
            else if (rem == 1) cp_wait<1>();
            else               cp_wait<0>();
        } else {
            if (rem >= 1)      cp_wait<1>();
            else               cp_wait<0>();
        }
        __syncthreads();
        if (NST >= 3 && kt + NST - 1 < KT) load_tile(kt + NST - 1);   // overlap

        const __half* sA  = (const __half*)(dsm + (size_t)(kt % NST) * STAGE);
        const __half* sAl = sA + 5120;
        const __half* sB  = sA + ABYTES / 2;
        const __half* sBl = sB + 4352;

#pragma unroll
        for (int kk = 0; kk < 32; kk += 16) {
            wmma::fragment<wmma::matrix_a, 16, 16, 16, __half, wmma::row_major> ah[2], al[2];
#pragma unroll
            for (int i = 0; i < 2; i++) {
                wmma::load_matrix_sync(ah[i], sA  + (wm * 32 + i * 16) * 40 + kk, 40);
                if (TERMS >= 2)
                    wmma::load_matrix_sync(al[i], sAl + (wm * 32 + i * 16) * 40 + kk, 40);
            }
#pragma unroll
            for (int j = 0; j < 4; j++) {
                wmma::fragment<wmma::matrix_b, 16, 16, 16, __half, wmma::row_major> bh, bl;
                wmma::load_matrix_sync(bh, sB + kk * 136 + wn * 64 + j * 16, 136);
                if (TERMS == 3)
                    wmma::load_matrix_sync(bl, sBl + kk * 136 + wn * 64 + j * 16, 136);
#pragma unroll
                for (int i = 0; i < 2; i++) {
                    wmma::mma_sync(acc[i][j], ah[i], bh, acc[i][j]);
                    if (TERMS >= 2)
                        wmma::mma_sync(acc[i][j], al[i], bh, acc[i][j]);
                    if (TERMS == 3)
                        wmma::mma_sync(acc[i][j], ah[i], bl, acc[i][j]);
                }
            }
        }
        if (NST == 2) {
            __syncthreads();
            if (kt + 2 < KT) load_tile(kt + 2);
        }
    }
    if (NST >= 3) __syncthreads();

    // epilogue via per-warp smem staging (guarded N, epilogue ops); ldm=20
    float* sc = sC + warpId * 320;
#pragma unroll
    for (int i = 0; i < 2; i++) {
#pragma unroll
        for (int j = 0; j < 4; j++) {
            wmma::store_matrix_sync(sc, acc[i][j], 20, wmma::mem_row_major);
            __syncwarp();
#pragma unroll
            for (int e = lane; e < 256; e += 32) {
                int r = e >> 4, c = e & 15;
                int gr = bm + wm * 32 + i * 16 + r;
                int gc = bn + wn * 64 + j * 16 + c;
                if (gc < N) {
                    float v = sc[r * 20 + c];
                    if (mode == 1)      v += bias[gc];
                    else if (mode == 2) v += addsrc[(size_t)gr * N + gc];
                    C[(size_t)gr * N + gc] = v;
                }
            }
            __syncwarp();
        }
    }
}

// ---------------- residual + K-split(4) reduce: h += p0+p1+p2+p3 (+hi/lo) ---
__global__ void resid_add_kernel(float* __restrict__ h,
                                 const float* __restrict__ p,
                                 __half* __restrict__ hhi, __half* __restrict__ hlo) {
    int i = blockIdx.x * 256 + threadIdx.x;
    const size_t PS = (size_t)BSS * DD / 4;   // in float4 units
    float4 a = ((float4*)h)[i];
#pragma unroll
    for (int z = 0; z < 4; z++) {
        float4 b = ((const float4*)p)[z * PS + i];
        a.x += b.x; a.y += b.y; a.z += b.z; a.w += b.w;
    }
    ((float4*)h)[i] = a;
    __half h0, l0, h1, l1, h2, l2, h3, l3;
    split_f16(a.x, h0, l0); split_f16(a.y, h1, l1);
    split_f16(a.z, h2, l2); split_f16(a.w, h3, l3);
    ((__half2*)hhi)[i * 2]     = __halves2half2(h0, h1);
    ((__half2*)hhi)[i * 2 + 1] = __halves2half2(h2, h3);
    ((__half2*)hlo)[i * 2]     = __halves2half2(l0, l1);
    ((__half2*)hlo)[i * 2 + 1] = __halves2half2(l2, l3);
}

// ---------------- K2: conv4 + temb + silu + LN + xnorm (+ fp16 hi/lo) -------
__global__ void conv_silu_ln_kernel(const float* __restrict__ proj,
                                    const int* __restrict__ t,
                                    const float* __restrict__ temb,
                                    const float* __restrict__ cw,
                                    const float* __restrict__ cb,
                                    const float* __restrict__ g,
                                    const float* __restrict__ bb,
                                    float* __restrict__ xc_out,
                                    __half* __restrict__ xchi,
                                    __half* __restrict__ xclo,
                                    float* __restrict__ xnorm_out) {
    __shared__ float ssum[8], ssq[8];
    int bs = blockIdx.x;
    int b = bs >> 10;
    int s = bs & (SS - 1);
    const float* te = temb + (size_t)t[b] * DII;

    float vals[4];
    float lsum = 0.f, lsq = 0.f;
#pragma unroll
    for (int u = 0; u < 4; u++) {
        int di = threadIdx.x + u * 256;
        float acc = cb[di];
        float tv = te[di];
        const float* w = cw + di * 4;
#pragma unroll
        for (int k = 0; k < 4; k++) {
            int sp = s - 3 + k;
            if (sp >= 0)
                acc += (proj[((size_t)(b * SS + sp)) * (2 * DII) + di] + tv) * w[k];
        }
        float v = silu_f(acc);
        vals[u] = v;
        lsum += v; lsq += v * v;
    }
    int wid = threadIdx.x >> 5, lane = threadIdx.x & 31;
    lsum = warp_sum(lsum);
    lsq  = warp_sum(lsq);
    if (lane == 0) { ssum[wid] = lsum; ssq[wid] = lsq; }
    __syncthreads();
    float tot = 0.f, totq = 0.f;
#pragma unroll
    for (int w = 0; w < 8; w++) { tot += ssum[w]; totq += ssq[w]; }
    float mu = tot * (1.0f / DII);
    float var = totq * (1.0f / DII) - mu * mu;
    float rstd = rsqrtf(var + 1e-5f);

    float nrm = 0.f;
#pragma unroll
    for (int u = 0; u < 4; u++) {
        int di = threadIdx.x + u * 256;
        float o = (vals[u] - mu) * rstd * g[di] + bb[di];
        size_t gi = (size_t)bs * DII + di;
        xc_out[gi] = o;
        __half hi_, lo_;
        split_f16(o, hi_, lo_);
        xchi[gi] = hi_;
        xclo[gi] = lo_;
        nrm += o * o;
    }
    __syncthreads();
    nrm = warp_sum(nrm);
    if (lane == 0) ssum[wid] = nrm;
    __syncthreads();
    if (threadIdx.x == 0) {
        float tn = 0.f;
#pragma unroll
        for (int w = 0; w < 8; w++) tn += ssum[w];
        xnorm_out[bs] = fminf(sqrtf(tn), 1.0f);
    }
}

// ---------------- K3b: coefficient prep (sums 8 K-split xproj partials) -----
__global__ void coeff_kernel(const float* __restrict__ p,   // 8 parts of [BSS,48]
                             const float* __restrict__ xnorm,
                             const float* __restrict__ dtw,
                             const float* __restrict__ dtb,
                             const float* __restrict__ alog,
                             float* __restrict__ coeff) {
    int row = blockIdx.x * 16 + (threadIdx.x >> 4);
    int i = threadIdx.x & 15;
    const float* pr0 = p + (size_t)row * 48;
    const size_t PS = (size_t)BSS * 48;

    float bm = 0.f, cm = 0.f;
    float dtp[16];
#pragma unroll
    for (int j = 0; j < 16; j++) dtp[j] = 0.f;
#pragma unroll
    for (int z = 0; z < 8; z++) {
        const float* pr = pr0 + z * PS;
        bm += pr[i];
        cm += pr[16 + i];
#pragma unroll
        for (int j = 0; j < 16; j++) dtp[j] += pr[32 + j];
    }
    float acc = dtb[i];
#pragma unroll
    for (int j = 0; j < 16; j++) acc += dtp[j] * dtw[i * 16 + j];
    float dt = tanhf(acc) * 0.01f;
    float ad = 1.0f + dt * (-tanhf(alog[i]));
    size_t base = (size_t)row * 48;
    coeff[base + i]      = ad;
    coeff[base + 16 + i] = bm * xnorm[row];
    coeff[base + 32 + i] = cm;
}

// ---------------- K4: SSM scan v5 — no shfl/store in hot loop ---------------
#define SCHUNK 32
__global__ void scan_kernel(const float* __restrict__ xc,
                            const float* __restrict__ coeff,
                            const float* __restrict__ proj,
                            const float* __restrict__ dparam,
                            __half* __restrict__ yhi, __half* __restrict__ ylo) {
    __shared__ __align__(16) float stg[2][2][SCHUNK * 64];   // [warp][buf][...]
    __shared__ __align__(16) float yb[2][SCHUNK * 32];       // partial y per warp
    const int blk = blockIdx.x;
    const int b   = blk >> 6;
    const int di0 = (blk & 63) << 4;
    const int tid = threadIdx.x;
    const int w   = tid >> 5;
    const int lane = tid & 31;
    const int dw  = lane >> 2;       // 0..7 local di (hot loop role)
    const int sg  = lane & 3;        // state group
    const int dq  = lane & 7;        // local di owned in reduction role

    const float* cbase = coeff + (size_t)b * SS * 48;
    const float* xw    = xc    + (size_t)b * SS * DII + di0 + w * 8;
    const float* gw    = proj  + (size_t)b * SS * (2 * DII) + DII + di0 + w * 8;
    const uint32_t sb0 = smem_u32(&stg[w][0][0]);
    const uint32_t sb1 = smem_u32(&stg[w][1][0]);

    auto load_chunk = [&](int c, int buf) {
        const int t0 = c * SCHUNK;
        const uint32_t dstb = buf ? sb1 : sb0;
#pragma unroll
        for (int k = 0; k < 16; k++) {
            int id = k * 32 + lane;
            int s = id >> 4, j = id & 15;
            uint32_t dst = dstb + (uint32_t)(s * 256 + j * 16);
            int t = t0 + s;
            const float* src;
            if (j < 12)      src = cbase + (size_t)t * 48 + j * 4;
            else if (j < 14) src = xw + (size_t)t * DII + (j - 12) * 4;
            else             src = gw + (size_t)t * (2 * DII) + (j - 14) * 4;
            cp_async16(dst, src);
        }
        cp_commit();
    };

    float h0 = 0.f, h1 = 0.f, h2 = 0.f, h3 = 0.f;
    const float dpq = dparam[di0 + w * 8 + dq];      // reduction-role dp
    __half* yh = yhi + (size_t)b * SS * DII + di0 + w * 8 + dq;
    __half* yl = ylo + (size_t)b * SS * DII + di0 + w * 8 + dq;

    load_chunk(0, 0);

    const int NC = SS / SCHUNK;
    for (int c = 0; c < NC; c++) {
        if (c + 1 < NC) {
            load_chunk(c + 1, (c + 1) & 1);
            cp_wait<1>();
        } else {
            cp_wait<0>();
        }
        __syncwarp();
        const float* buf = &stg[w][c & 1][0];
        float* yp = &yb[w][0];
#pragma unroll
        for (int s = 0; s < SCHUNK; s++) {
            const float* st = buf + s * 64;
            float4 ad = *(const float4*)(st + sg * 4);
            float4 bd = *(const float4*)(st + 16 + sg * 4);
            float4 cc = *(const float4*)(st + 32 + sg * 4);
            float xv = st[48 + dw];

            h0 = fminf(fmaxf(h0 * ad.x + bd.x * xv, -10.f), 10.f);
            h1 = fminf(fmaxf(h1 * ad.y + bd.y * xv, -10.f), 10.f);
            h2 = fminf(fmaxf(h2 * ad.z + bd.z * xv, -10.f), 10.f);
            h3 = fminf(fmaxf(h3 * ad.w + bd.w * xv, -10.f), 10.f);

            yp[s * 32 + lane] = cc.x * h0 + cc.y * h1 + cc.z * h2 + cc.w * h3;
        }
        __syncwarp();
        const int t0 = c * SCHUNK;
#pragma unroll
        for (int r = 0; r < 8; r++) {
            int s = r * 4 + (lane >> 3);
            float4 pq = *(const float4*)(&yb[w][s * 32 + dq * 4]);
            const float* st = buf + s * 64;
            float xv = st[48 + dq];
            float gv = st[56 + dq];
            float yo = (pq.x + pq.y + pq.z + pq.w + dpq * xv) * silu_f(gv);
            __half hi_, lo_;
            split_f16(yo, hi_, lo_);
            size_t go = (size_t)(t0 + s) * DII;
            yh[go] = hi_;
            yl[go] = lo_;
        }
        __syncwarp();
    }
}

// ---------------- orchestration ---------------------------------------------
extern "C" void kernel_launch(void* const* d_in, const int* in_sizes, int n_in,
                              void* d_out, int out_size) {
    (void)in_sizes; (void)n_in; (void)out_size;
    const int*   x        = (const int*)  d_in[0];
    const int*   t        = (const int*)  d_in[1];
    const float* emb      = (const float*)d_in[2];
    const float* pos      = (const float*)d_in[3];
    const float* temb     = (const float*)d_in[4];
    const float* in_w     = (const float*)d_in[5];
    const float* conv_w   = (const float*)d_in[6];
    const float* conv_b   = (const float*)d_in[7];
    const float* ln_g     = (const float*)d_in[8];
    const float* ln_b     = (const float*)d_in[9];
    const float* xproj_w  = (const float*)d_in[10];
    const float* dt_w     = (const float*)d_in[11];
    const float* dt_b     = (const float*)d_in[12];
    const float* a_log    = (const float*)d_in[13];
    const float* d_param  = (const float*)d_in[14];
    const float* out_pw   = (const float*)d_in[15];
    const float* out_w    = (const float*)d_in[16];
    const float* out_b    = (const float*)d_in[17];
    float* out = (float*)d_out;

    static float *p_h = nullptr, *p_proj = nullptr, *p_xc = nullptr,
                 *p_coeff = nullptr, *p_xn = nullptr, *p_part = nullptr;
    static __half *p_hhi = nullptr, *p_hlo = nullptr, *p_xchi = nullptr, *p_xclo = nullptr,
                  *p_yhi = nullptr, *p_ylo = nullptr, *p_bhi = nullptr,
                  *p_wihi = nullptr, *p_wilo = nullptr, *p_wohi = nullptr, *p_wolo = nullptr,
                  *p_wxhi = nullptr, *p_wxlo = nullptr;
    if (!p_h) {
        cudaGetSymbolAddress((void**)&p_h, g_h);
        cudaGetSymbolAddress((void**)&p_proj, g_proj);
        cudaGetSymbolAddress((void**)&p_xc, g_xc);
        cudaGetSymbolAddress((void**)&p_coeff, g_coeff);
        cudaGetSymbolAddress((void**)&p_xn, g_xnorm);
        cudaGetSymbolAddress((void**)&p_part, g_part);
        cudaGetSymbolAddress((void**)&p_hhi, g_Hhi);
        cudaGetSymbolAddress((void**)&p_hlo, g_Hlo);
        cudaGetSymbolAddress((void**)&p_xchi, g_XChi);
        cudaGetSymbolAddress((void**)&p_xclo, g_XClo);
        cudaGetSymbolAddress((void**)&p_yhi, g_Yhi);
        cudaGetSymbolAddress((void**)&p_ylo, g_Ylo);
        cudaGetSymbolAddress((void**)&p_bhi, g_Bhi);
        cudaGetSymbolAddress((void**)&p_wihi, g_Wihi);
        cudaGetSymbolAddress((void**)&p_wilo, g_Wilo);
        cudaGetSymbolAddress((void**)&p_wohi, g_Wohi);
        cudaGetSymbolAddress((void**)&p_wolo, g_Wolo);
        cudaGetSymbolAddress((void**)&p_wxhi, g_Wxhi);
        cudaGetSymbolAddress((void**)&p_wxlo, g_Wxlo);
        cudaFuncSetAttribute(gemm_f16<3>, cudaFuncAttributeMaxDynamicSharedMemorySize, 2 * ST3);
        cudaFuncSetAttribute(gemm_f16<1>, cudaFuncAttributeMaxDynamicSharedMemorySize, 4 * ST1);
    }

    embed_kernel<<<BSS, 128>>>(x, emb, pos, p_h, p_hhi, p_hlo);

    // ---- batched weight splits (once per launch, all layers folded in K) ----
    splitB_kernel<<<(NL * DD * 2 * DII / 4) / 256, 256>>>(
        in_w, p_wihi, p_wilo, NL * DD, 2 * DII, 2 * DII);
    splitB_kernel<<<(NL * DII * DD / 4) / 256, 256>>>(
        out_pw, p_wohi, p_wolo, NL * DII, DD, DD);
    splitB_kernel<<<(NL * DII * 128 / 4) / 256, 256>>>(
        xproj_w, p_wxhi, p_wxlo, NL * DII, 48, 128);
    splitB_kernel<<<(DD * NPADV / 4) / 256, 256>>>(
        out_w, p_bhi, nullptr, DD, VV, NPADV);

    for (int l = 0; l < NL; l++) {
        // proj = h @ in_w[l]   (M=2048, N=2048, K=512), TERMS=3
        gemm_f16<3><<<dim3(BSS / 128, (2 * DII) / 128, 1), 256, 2 * ST3>>>(
            p_hhi, p_hlo, p_wihi + (size_t)l * DD * 2 * DII,
            p_wilo + (size_t)l * DD * 2 * DII, p_proj,
            BSS, 2 * DII, 2 * DII, DD, DD, nullptr, nullptr, 0);

        conv_silu_ln_kernel<<<BSS, 256>>>(
            p_proj, t, temb,
            conv_w + (size_t)l * DII * 4, conv_b + (size_t)l * DII,
            ln_g + (size_t)l * DII, ln_b + (size_t)l * DII,
            p_xc, p_xchi, p_xclo, p_xn);

        // p = xc @ xproj_w   (M=2048, N=48 pad 128, K=1024), K-split 8
        gemm_f16<3><<<dim3(BSS / 128, 1, 8), 256, 2 * ST3>>>(
            p_xchi, p_xclo, p_wxhi + (size_t)l * DII * 128,
            p_wxlo + (size_t)l * DII * 128, p_part,
            BSS, 48, 128, DII, DII / 8, nullptr, nullptr, 0);

        coeff_kernel<<<BSS / 16, 256>>>(
            p_part, p_xn,
            dt_w + (size_t)l * DSS * DSS, dt_b + (size_t)l * DSS,
            a_log + (size_t)l * DSS, p_coeff);

        scan_kernel<<<BB * (DII / 16), 64>>>(
            p_xc, p_coeff, p_proj, d_param + (size_t)l * DII, p_yhi, p_ylo);

        // h += yg @ out_proj_w[l]   (M=2048, N=512, K=1024), K-split 4 + reduce
        gemm_f16<3><<<dim3(BSS / 128, DD / 128, 4), 256, 2 * ST3>>>(
            p_yhi, p_ylo, p_wohi + (size_t)l * DII * DD,
            p_wolo + (size_t)l * DII * DD, p_part,
            BSS, DD, DD, DII, DII / 4, nullptr, nullptr, 0);
        resid_add_kernel<<<(BSS * DD / 4) / 256, 256>>>(p_h, p_part, p_hhi, p_hlo);
    }

    // logits = h @ out_w + out_b  (M=2048, N=50257 pad 50432, K=512), TERMS=1
    gemm_f16<1><<<dim3(BSS / 128, NPADV / 128, 1), 256, 4 * ST1>>>(
        p_hhi, nullptr, p_bhi, nullptr, out, BSS, VV, NPADV, DD, DD,
        out_b, nullptr, 1);
}

// round 17
// speedup vs baseline: 1.0326x; 1.0326x over previous
#include <cuda_runtime.h>
#include <cuda_fp16.h>
#include <mma.h>
#include <math.h>
#include <stdint.h>

using namespace nvcuda;

#define NL 4
#define DD 512
#define DII 1024
#define DSS 16
#define VV 50257
#define BB 2
#define SS 1024
#define BSS 2048    /* BB*SS */
#define NPADV 50432 /* VV padded to 128 */

// ---------------- scratch (static device globals; no allocations) ----------
__device__ __align__(256) float g_h[BSS * DD];
__device__ __align__(256) float g_proj[BSS * 2 * DII];
__device__ __align__(256) float g_xc[BSS * DII];
__device__ __align__(256) float g_coeff[BSS * 48];
__device__ __align__(256) float g_xnorm[BSS];
__device__ __align__(256) float g_part[4 * BSS * DD];   // out_pw split4 / xproj split8 partials
// fp16 hi/lo staging (split fused into producer kernels)
__device__ __align__(256) __half g_Hhi[BSS * DD];
__device__ __align__(256) __half g_Hlo[BSS * DD];
__device__ __align__(256) __half g_XChi[BSS * DII];
__device__ __align__(256) __half g_XClo[BSS * DII];
__device__ __align__(256) __half g_Yhi[BSS * DII];
__device__ __align__(256) __half g_Ylo[BSS * DII];
// per-weight fp16 buffers (all layers, split once per launch)
__device__ __align__(256) __half g_Wihi[NL * DD * 2 * DII];
__device__ __align__(256) __half g_Wilo[NL * DD * 2 * DII];
__device__ __align__(256) __half g_Wohi[NL * DII * DD];
__device__ __align__(256) __half g_Wolo[NL * DII * DD];
__device__ __align__(256) __half g_Wxhi[NL * DII * 128];
__device__ __align__(256) __half g_Wxlo[NL * DII * 128];
__device__ __align__(256) __half g_Bhi[NPADV * DD];     // logits weight (hi only)

// ---------------- helpers ---------------------------------------------------
__device__ __forceinline__ float warp_sum(float v) {
#pragma unroll
    for (int o = 16; o > 0; o >>= 1) v += __shfl_xor_sync(0xffffffffu, v, o);
    return v;
}
__device__ __forceinline__ float silu_f(float x) {
    return x * (1.0f / (1.0f + __expf(-x)));
}
__device__ __forceinline__ void split_f16(float x, __half& hi, __half& lo) {
    hi = __float2half_rn(x);
    lo = __float2half_rn(x - __half2float(hi));
}
__device__ __forceinline__ uint32_t smem_u32(const void* p) {
    uint32_t a;
    asm("{ .reg .u64 t; cvta.to.shared.u64 t, %1; cvt.u32.u64 %0, t; }" : "=r"(a) : "l"(p));
    return a;
}
__device__ __forceinline__ void cp_async16(uint32_t dst, const void* src) {
    asm volatile("cp.async.cg.shared.global [%0], [%1], 16;" :: "r"(dst), "l"(src));
}
__device__ __forceinline__ void cp_commit() {
    asm volatile("cp.async.commit_group;" ::: "memory");
}
template<int N> __device__ __forceinline__ void cp_wait() {
    asm volatile("cp.async.wait_group %0;" :: "n"(N) : "memory");
}

// ---------------- K0: embedding gather + pos (+ fp16 hi/lo) -----------------
__global__ void embed_kernel(const int* __restrict__ x, const float* __restrict__ emb,
                             const float* __restrict__ pos, float* __restrict__ h,
                             __half* __restrict__ hhi, __half* __restrict__ hlo) {
    int bs = blockIdx.x;
    int s  = bs & (SS - 1);
    int tok = x[bs];
    const float4* e4 = (const float4*)(emb + (size_t)tok * DD);
    const float4* p4 = (const float4*)(pos + (size_t)s * DD);
    int i = threadIdx.x;
    float4 a = e4[i], p = p4[i];
    float4 v = make_float4(a.x + p.x, a.y + p.y, a.z + p.z, a.w + p.w);
    size_t gi = (size_t)bs * (DD / 4) + i;
    ((float4*)h)[gi] = v;
    __half h0, l0, h1, l1, h2, l2, h3, l3;
    split_f16(v.x, h0, l0); split_f16(v.y, h1, l1);
    split_f16(v.z, h2, l2); split_f16(v.w, h3, l3);
    ((__half2*)hhi)[gi * 2]     = __halves2half2(h0, h1);
    ((__half2*)hhi)[gi * 2 + 1] = __halves2half2(h2, h3);
    ((__half2*)hlo)[gi * 2]     = __halves2half2(l0, l1);
    ((__half2*)hlo)[gi * 2 + 1] = __halves2half2(l2, l3);
}

// ---------------- prepass: fp32 B[K,N] -> fp16 hi(/lo) [K,NPAD] (padded) ----
// float4 fast path when row-aligned and in-bounds.
__global__ void splitB_kernel(const float* __restrict__ B,
                              __half* __restrict__ hi, __half* __restrict__ lo,
                              int K, int N, int NPAD) {
    int idx = blockIdx.x * 256 + threadIdx.x;        // per 4 outputs
    int k = idx / (NPAD >> 2);
    int n4 = (idx - k * (NPAD >> 2)) << 2;
    size_t src = (size_t)k * N + n4;
    float v0, v1, v2, v3;
    if ((n4 + 3 < N) && ((src & 3) == 0)) {
        float4 d = __ldg((const float4*)(B + src));
        v0 = d.x; v1 = d.y; v2 = d.z; v3 = d.w;
    } else {
        v0 = (n4     < N) ? __ldg(B + src)     : 0.0f;
        v1 = (n4 + 1 < N) ? __ldg(B + src + 1) : 0.0f;
        v2 = (n4 + 2 < N) ? __ldg(B + src + 2) : 0.0f;
        v3 = (n4 + 3 < N) ? __ldg(B + src + 3) : 0.0f;
    }
    __half h0, l0, h1, l1, h2, l2, h3, l3;
    split_f16(v0, h0, l0); split_f16(v1, h1, l1);
    split_f16(v2, h2, l2); split_f16(v3, h3, l3);
    size_t o = ((size_t)k * NPAD + n4) >> 1;
    ((__half2*)hi)[o]     = __halves2half2(h0, h1);
    ((__half2*)hi)[o + 1] = __halves2half2(h2, h3);
    if (lo) {
        ((__half2*)lo)[o]     = __halves2half2(l0, l1);
        ((__half2*)lo)[o + 1] = __halves2half2(l2, l3);
    }
}

// ---------------- GEMM: fp16 wmma, TERMS=3 (2-stage) or 1 (3-stage) ---------
// C[M,N] = (Ahi[+Alo])[M,lda] @ Bhi(+Blo)[*,ldb]; Kloop columns per z-part.
// gridDim.z = K-split parts; part z writes to C + z*M*N (mode 0 only).
// mode 0: plain, 1: +bias[n], 2: += addsrc[m,n]. M%128==0, Kloop%32==0, KT>=2.
// 2 CTAs/SM; 128x128 tile, 8 warps of 32x64.
#define ST3 37888
#define ST1 18944

template<int TERMS>
__global__ __launch_bounds__(256, 2)
void gemm_f16(const __half* __restrict__ Ahi, const __half* __restrict__ Alo,
              const __half* __restrict__ Bhi, const __half* __restrict__ Blo,
              float* __restrict__ C, int M, int N, int ldb, int lda, int Kloop,
              const float* __restrict__ bias, const float* __restrict__ addsrc,
              int mode) {
    constexpr int ABYTES = (TERMS >= 2) ? 20480 : 10240;
    constexpr int STAGE  = ABYTES + 8704 * ((TERMS == 3) ? 2 : 1);
    constexpr int NST    = (TERMS == 1) ? 3 : 2;
    extern __shared__ __align__(128) char dsm[];
    __shared__ __align__(128) float sC[8 * 16 * 20];

    const int tid = threadIdx.x;
    const int warpId = tid >> 5, lane = tid & 31;
    const int wm = warpId >> 1;        // 0..3 -> 32-row slab
    const int wn = warpId & 1;         // 0..1 -> 64-col slab
    const int bm = blockIdx.x * 128;
    const int bn = blockIdx.y * 128;
    const int koff = blockIdx.z * Kloop;
    const int KT = Kloop >> 5;
    const uint32_t sbase = smem_u32(dsm);
    if (blockIdx.z) C += (size_t)blockIdx.z * M * N;

    wmma::fragment<wmma::accumulator, 16, 16, 16, float> acc[2][4];
#pragma unroll
    for (int i = 0; i < 2; i++)
#pragma unroll
        for (int j = 0; j < 4; j++) wmma::fill_fragment(acc[i][j], 0.0f);

    auto load_tile = [&](int kt) {
        const uint32_t base = sbase + (uint32_t)(kt % NST) * STAGE;
        const int k0 = koff + (kt << 5);
#pragma unroll
        for (int i = 0; i < 2; i++) {
            int idx = i * 256 + tid;
            int row = idx >> 2, c = idx & 3;
            uint32_t off = (uint32_t)(row * 40 + c * 8) * 2;
            size_t go = (size_t)(bm + row) * lda + k0 + c * 8;
            cp_async16(base + off, Ahi + go);
            if (TERMS >= 2)
                cp_async16(base + 10240 + off, Alo + go);
        }
#pragma unroll
        for (int i = 0; i < 2; i++) {
            int idx = i * 256 + tid;
            int row = idx >> 4, c = idx & 15;
            uint32_t off = (uint32_t)(row * 136 + c * 8) * 2;
            size_t go = (size_t)(k0 + row) * ldb + bn + c * 8;
            cp_async16(base + ABYTES + off, Bhi + go);
            if (TERMS == 3)
                cp_async16(base + ABYTES + 8704 + off, Blo + go);
        }
        cp_commit();
    };

    load_tile(0);
    if (KT > 1) load_tile(1);

    for (int kt = 0; kt < KT; kt++) {
        if (kt + 1 < KT) cp_wait<1>(); else cp_wait<0>();
        __syncthreads();
        if (NST == 3 && kt + 2 < KT) load_tile(kt + 2);   // overlap loads w/ MMAs

        const __half* sA  = (const __half*)(dsm + (size_t)(kt % NST) * STAGE);
        const __half* sAl = sA + 5120;
        const __half* sB  = sA + ABYTES / 2;
        const __half* sBl = sB + 4352;

#pragma unroll
        for (int kk = 0; kk < 32; kk += 16) {
            wmma::fragment<wmma::matrix_a, 16, 16, 16, __half, wmma::row_major> ah[2], al[2];
#pragma unroll
            for (int i = 0; i < 2; i++) {
                wmma::load_matrix_sync(ah[i], sA  + (wm * 32 + i * 16) * 40 + kk, 40);
                if (TERMS >= 2)
                    wmma::load_matrix_sync(al[i], sAl + (wm * 32 + i * 16) * 40 + kk, 40);
            }
#pragma unroll
            for (int j = 0; j < 4; j++) {
                wmma::fragment<wmma::matrix_b, 16, 16, 16, __half, wmma::row_major> bh, bl;
                wmma::load_matrix_sync(bh, sB + kk * 136 + wn * 64 + j * 16, 136);
                if (TERMS == 3)
                    wmma::load_matrix_sync(bl, sBl + kk * 136 + wn * 64 + j * 16, 136);
#pragma unroll
                for (int i = 0; i < 2; i++) {
                    wmma::mma_sync(acc[i][j], ah[i], bh, acc[i][j]);
                    if (TERMS >= 2)
                        wmma::mma_sync(acc[i][j], al[i], bh, acc[i][j]);
                    if (TERMS == 3)
                        wmma::mma_sync(acc[i][j], ah[i], bl, acc[i][j]);
                }
            }
        }
        if (NST == 2) {
            __syncthreads();
            if (kt + 2 < KT) load_tile(kt + 2);
        }
    }
    if (NST == 3) __syncthreads();

    // epilogue via per-warp smem staging (guarded N, epilogue ops); ldm=20
    float* sc = sC + warpId * 320;
#pragma unroll
    for (int i = 0; i < 2; i++) {
#pragma unroll
        for (int j = 0; j < 4; j++) {
            wmma::store_matrix_sync(sc, acc[i][j], 20, wmma::mem_row_major);
            __syncwarp();
#pragma unroll
            for (int e = lane; e < 256; e += 32) {
                int r = e >> 4, c = e & 15;
                int gr = bm + wm * 32 + i * 16 + r;
                int gc = bn + wn * 64 + j * 16 + c;
                if (gc < N) {
                    float v = sc[r * 20 + c];
                    if (mode == 1)      v += bias[gc];
                    else if (mode == 2) v += addsrc[(size_t)gr * N + gc];
                    C[(size_t)gr * N + gc] = v;
                }
            }
            __syncwarp();
        }
    }
}

// ---------------- residual + K-split(4) reduce: h += p0+p1+p2+p3 (+hi/lo) ---
__global__ void resid_add_kernel(float* __restrict__ h,
                                 const float* __restrict__ p,
                                 __half* __restrict__ hhi, __half* __restrict__ hlo) {
    int i = blockIdx.x * 256 + threadIdx.x;
    const size_t PS = (size_t)BSS * DD / 4;   // in float4 units
    float4 a = ((float4*)h)[i];
#pragma unroll
    for (int z = 0; z < 4; z++) {
        float4 b = ((const float4*)p)[z * PS + i];
        a.x += b.x; a.y += b.y; a.z += b.z; a.w += b.w;
    }
    ((float4*)h)[i] = a;
    __half h0, l0, h1, l1, h2, l2, h3, l3;
    split_f16(a.x, h0, l0); split_f16(a.y, h1, l1);
    split_f16(a.z, h2, l2); split_f16(a.w, h3, l3);
    ((__half2*)hhi)[i * 2]     = __halves2half2(h0, h1);
    ((__half2*)hhi)[i * 2 + 1] = __halves2half2(h2, h3);
    ((__half2*)hlo)[i * 2]     = __halves2half2(l0, l1);
    ((__half2*)hlo)[i * 2 + 1] = __halves2half2(l2, l3);
}

// ---------------- K2: conv4 + temb + silu + LN + xnorm (+ fp16 hi/lo) -------
__global__ void conv_silu_ln_kernel(const float* __restrict__ proj,
                                    const int* __restrict__ t,
                                    const float* __restrict__ temb,
                                    const float* __restrict__ cw,
                                    const float* __restrict__ cb,
                                    const float* __restrict__ g,
                                    const float* __restrict__ bb,
                                    float* __restrict__ xc_out,
                                    __half* __restrict__ xchi,
                                    __half* __restrict__ xclo,
                                    float* __restrict__ xnorm_out) {
    __shared__ float ssum[8], ssq[8];
    int bs = blockIdx.x;
    int b = bs >> 10;
    int s = bs & (SS - 1);
    const float* te = temb + (size_t)t[b] * DII;

    float vals[4];
    float lsum = 0.f, lsq = 0.f;
#pragma unroll
    for (int u = 0; u < 4; u++) {
        int di = threadIdx.x + u * 256;
        float acc = cb[di];
        float tv = te[di];
        const float* w = cw + di * 4;
#pragma unroll
        for (int k = 0; k < 4; k++) {
            int sp = s - 3 + k;
            if (sp >= 0)
                acc += (proj[((size_t)(b * SS + sp)) * (2 * DII) + di] + tv) * w[k];
        }
        float v = silu_f(acc);
        vals[u] = v;
        lsum += v; lsq += v * v;
    }
    int wid = threadIdx.x >> 5, lane = threadIdx.x & 31;
    lsum = warp_sum(lsum);
    lsq  = warp_sum(lsq);
    if (lane == 0) { ssum[wid] = lsum; ssq[wid] = lsq; }
    __syncthreads();
    float tot = 0.f, totq = 0.f;
#pragma unroll
    for (int w = 0; w < 8; w++) { tot += ssum[w]; totq += ssq[w]; }
    float mu = tot * (1.0f / DII);
    float var = totq * (1.0f / DII) - mu * mu;
    float rstd = rsqrtf(var + 1e-5f);

    float nrm = 0.f;
#pragma unroll
    for (int u = 0; u < 4; u++) {
        int di = threadIdx.x + u * 256;
        float o = (vals[u] - mu) * rstd * g[di] + bb[di];
        size_t gi = (size_t)bs * DII + di;
        xc_out[gi] = o;
        __half hi_, lo_;
        split_f16(o, hi_, lo_);
        xchi[gi] = hi_;
        xclo[gi] = lo_;
        nrm += o * o;
    }
    __syncthreads();
    nrm = warp_sum(nrm);
    if (lane == 0) ssum[wid] = nrm;
    __syncthreads();
    if (threadIdx.x == 0) {
        float tn = 0.f;
#pragma unroll
        for (int w = 0; w < 8; w++) tn += ssum[w];
        xnorm_out[bs] = fminf(sqrtf(tn), 1.0f);
    }
}

// ---------------- K3b: coefficient prep (sums 8 K-split xproj partials) -----
__global__ void coeff_kernel(const float* __restrict__ p,   // 8 parts of [BSS,48]
                             const float* __restrict__ xnorm,
                             const float* __restrict__ dtw,
                             const float* __restrict__ dtb,
                             const float* __restrict__ alog,
                             float* __restrict__ coeff) {
    int row = blockIdx.x * 16 + (threadIdx.x >> 4);
    int i = threadIdx.x & 15;
    const float* pr0 = p + (size_t)row * 48;
    const size_t PS = (size_t)BSS * 48;

    float bm = 0.f, cm = 0.f;
    float dtp[16];
#pragma unroll
    for (int j = 0; j < 16; j++) dtp[j] = 0.f;
#pragma unroll
    for (int z = 0; z < 8; z++) {
        const float* pr = pr0 + z * PS;
        bm += pr[i];
        cm += pr[16 + i];
#pragma unroll
        for (int j = 0; j < 16; j++) dtp[j] += pr[32 + j];
    }
    float acc = dtb[i];
#pragma unroll
    for (int j = 0; j < 16; j++) acc += dtp[j] * dtw[i * 16 + j];
    float dt = tanhf(acc) * 0.01f;
    float ad = 1.0f + dt * (-tanhf(alog[i]));
    size_t base = (size_t)row * 48;
    coeff[base + i]      = ad;
    coeff[base + 16 + i] = bm * xnorm[row];
    coeff[base + 32 + i] = cm;
}

// ---------------- K4: SSM scan v5 — no shfl/store in hot loop ---------------
#define SCHUNK 32
__global__ void scan_kernel(const float* __restrict__ xc,
                            const float* __restrict__ coeff,
                            const float* __restrict__ proj,
                            const float* __restrict__ dparam,
                            __half* __restrict__ yhi, __half* __restrict__ ylo) {
    __shared__ __align__(16) float stg[2][2][SCHUNK * 64];   // [warp][buf][...]
    __shared__ __align__(16) float yb[2][SCHUNK * 32];       // partial y per warp
    const int blk = blockIdx.x;
    const int b   = blk >> 6;
    const int di0 = (blk & 63) << 4;
    const int tid = threadIdx.x;
    const int w   = tid >> 5;
    const int lane = tid & 31;
    const int dw  = lane >> 2;       // 0..7 local di (hot loop role)
    const int sg  = lane & 3;        // state group
    const int dq  = lane & 7;        // local di owned in reduction role

    const float* cbase = coeff + (size_t)b * SS * 48;
    const float* xw    = xc    + (size_t)b * SS * DII + di0 + w * 8;
    const float* gw    = proj  + (size_t)b * SS * (2 * DII) + DII + di0 + w * 8;
    const uint32_t sb0 = smem_u32(&stg[w][0][0]);
    const uint32_t sb1 = smem_u32(&stg[w][1][0]);

    auto load_chunk = [&](int c, int buf) {
        const int t0 = c * SCHUNK;
        const uint32_t dstb = buf ? sb1 : sb0;
#pragma unroll
        for (int k = 0; k < 16; k++) {
            int id = k * 32 + lane;
            int s = id >> 4, j = id & 15;
            uint32_t dst = dstb + (uint32_t)(s * 256 + j * 16);
            int t = t0 + s;
            const float* src;
            if (j < 12)      src = cbase + (size_t)t * 48 + j * 4;
            else if (j < 14) src = xw + (size_t)t * DII + (j - 12) * 4;
            else             src = gw + (size_t)t * (2 * DII) + (j - 14) * 4;
            cp_async16(dst, src);
        }
        cp_commit();
    };

    float h0 = 0.f, h1 = 0.f, h2 = 0.f, h3 = 0.f;
    const float dpq = dparam[di0 + w * 8 + dq];      // reduction-role dp
    __half* yh = yhi + (size_t)b * SS * DII + di0 + w * 8 + dq;
    __half* yl = ylo + (size_t)b * SS * DII + di0 + w * 8 + dq;

    load_chunk(0, 0);

    const int NC = SS / SCHUNK;
    for (int c = 0; c < NC; c++) {
        if (c + 1 < NC) {
            load_chunk(c + 1, (c + 1) & 1);
            cp_wait<1>();
        } else {
            cp_wait<0>();
        }
        __syncwarp();
        const float* buf = &stg[w][c & 1][0];
        float* yp = &yb[w][0];
#pragma unroll
        for (int s = 0; s < SCHUNK; s++) {
            const float* st = buf + s * 64;
            float4 ad = *(const float4*)(st + sg * 4);
            float4 bd = *(const float4*)(st + 16 + sg * 4);
            float4 cc = *(const float4*)(st + 32 + sg * 4);
            float xv = st[48 + dw];

            h0 = fminf(fmaxf(h0 * ad.x + bd.x * xv, -10.f), 10.f);
            h1 = fminf(fmaxf(h1 * ad.y + bd.y * xv, -10.f), 10.f);
            h2 = fminf(fmaxf(h2 * ad.z + bd.z * xv, -10.f), 10.f);
            h3 = fminf(fmaxf(h3 * ad.w + bd.w * xv, -10.f), 10.f);

            yp[s * 32 + lane] = cc.x * h0 + cc.y * h1 + cc.z * h2 + cc.w * h3;
        }
        __syncwarp();
        const int t0 = c * SCHUNK;
#pragma unroll
        for (int r = 0; r < 8; r++) {
            int s = r * 4 + (lane >> 3);
            float4 pq = *(const float4*)(&yb[w][s * 32 + dq * 4]);
            const float* st = buf + s * 64;
            float xv = st[48 + dq];
            float gv = st[56 + dq];
            float yo = (pq.x + pq.y + pq.z + pq.w + dpq * xv) * silu_f(gv);
            __half hi_, lo_;
            split_f16(yo, hi_, lo_);
            size_t go = (size_t)(t0 + s) * DII;
            yh[go] = hi_;
            yl[go] = lo_;
        }
        __syncwarp();
    }
}

// ---------------- orchestration ---------------------------------------------
extern "C" void kernel_launch(void* const* d_in, const int* in_sizes, int n_in,
                              void* d_out, int out_size) {
    (void)in_sizes; (void)n_in; (void)out_size;
    const int*   x        = (const int*)  d_in[0];
    const int*   t        = (const int*)  d_in[1];
    const float* emb      = (const float*)d_in[2];
    const float* pos      = (const float*)d_in[3];
    const float* temb     = (const float*)d_in[4];
    const float* in_w     = (const float*)d_in[5];
    const float* conv_w   = (const float*)d_in[6];
    const float* conv_b   = (const float*)d_in[7];
    const float* ln_g     = (const float*)d_in[8];
    const float* ln_b     = (const float*)d_in[9];
    const float* xproj_w  = (const float*)d_in[10];
    const float* dt_w     = (const float*)d_in[11];
    const float* dt_b     = (const float*)d_in[12];
    const float* a_log    = (const float*)d_in[13];
    const float* d_param  = (const float*)d_in[14];
    const float* out_pw   = (const float*)d_in[15];
    const float* out_w    = (const float*)d_in[16];
    const float* out_b    = (const float*)d_in[17];
    float* out = (float*)d_out;

    static float *p_h = nullptr, *p_proj = nullptr, *p_xc = nullptr,
                 *p_coeff = nullptr, *p_xn = nullptr, *p_part = nullptr;
    static __half *p_hhi = nullptr, *p_hlo = nullptr, *p_xchi = nullptr, *p_xclo = nullptr,
                  *p_yhi = nullptr, *p_ylo = nullptr, *p_bhi = nullptr,
                  *p_wihi = nullptr, *p_wilo = nullptr, *p_wohi = nullptr, *p_wolo = nullptr,
                  *p_wxhi = nullptr, *p_wxlo = nullptr;
    if (!p_h) {
        cudaGetSymbolAddress((void**)&p_h, g_h);
        cudaGetSymbolAddress((void**)&p_proj, g_proj);
        cudaGetSymbolAddress((void**)&p_xc, g_xc);
        cudaGetSymbolAddress((void**)&p_coeff, g_coeff);
        cudaGetSymbolAddress((void**)&p_xn, g_xnorm);
        cudaGetSymbolAddress((void**)&p_part, g_part);
        cudaGetSymbolAddress((void**)&p_hhi, g_Hhi);
        cudaGetSymbolAddress((void**)&p_hlo, g_Hlo);
        cudaGetSymbolAddress((void**)&p_xchi, g_XChi);
        cudaGetSymbolAddress((void**)&p_xclo, g_XClo);
        cudaGetSymbolAddress((void**)&p_yhi, g_Yhi);
        cudaGetSymbolAddress((void**)&p_ylo, g_Ylo);
        cudaGetSymbolAddress((void**)&p_bhi, g_Bhi);
        cudaGetSymbolAddress((void**)&p_wihi, g_Wihi);
        cudaGetSymbolAddress((void**)&p_wilo, g_Wilo);
        cudaGetSymbolAddress((void**)&p_wohi, g_Wohi);
        cudaGetSymbolAddress((void**)&p_wolo, g_Wolo);
        cudaGetSymbolAddress((void**)&p_wxhi, g_Wxhi);
        cudaGetSymbolAddress((void**)&p_wxlo, g_Wxlo);
        cudaFuncSetAttribute(gemm_f16<3>, cudaFuncAttributeMaxDynamicSharedMemorySize, 2 * ST3);
        cudaFuncSetAttribute(gemm_f16<1>, cudaFuncAttributeMaxDynamicSharedMemorySize, 3 * ST1);
    }

    embed_kernel<<<BSS, 128>>>(x, emb, pos, p_h, p_hhi, p_hlo);

    // ---- batched weight splits (once per launch, all layers folded in K) ----
    splitB_kernel<<<(NL * DD * 2 * DII / 4) / 256, 256>>>(
        in_w, p_wihi, p_wilo, NL * DD, 2 * DII, 2 * DII);
    splitB_kernel<<<(NL * DII * DD / 4) / 256, 256>>>(
        out_pw, p_wohi, p_wolo, NL * DII, DD, DD);
    splitB_kernel<<<(NL * DII * 128 / 4) / 256, 256>>>(
        xproj_w, p_wxhi, p_wxlo, NL * DII, 48, 128);
    splitB_kernel<<<(DD * NPADV / 4) / 256, 256>>>(
        out_w, p_bhi, nullptr, DD, VV, NPADV);

    for (int l = 0; l < NL; l++) {
        // proj = h @ in_w[l]   (M=2048, N=2048, K=512), TERMS=3
        gemm_f16<3><<<dim3(BSS / 128, (2 * DII) / 128, 1), 256, 2 * ST3>>>(
            p_hhi, p_hlo, p_wihi + (size_t)l * DD * 2 * DII,
            p_wilo + (size_t)l * DD * 2 * DII, p_proj,
            BSS, 2 * DII, 2 * DII, DD, DD, nullptr, nullptr, 0);

        conv_silu_ln_kernel<<<BSS, 256>>>(
            p_proj, t, temb,
            conv_w + (size_t)l * DII * 4, conv_b + (size_t)l * DII,
            ln_g + (size_t)l * DII, ln_b + (size_t)l * DII,
            p_xc, p_xchi, p_xclo, p_xn);

        // p = xc @ xproj_w   (M=2048, N=48 pad 128, K=1024), K-split 8
        gemm_f16<3><<<dim3(BSS / 128, 1, 8), 256, 2 * ST3>>>(
            p_xchi, p_xclo, p_wxhi + (size_t)l * DII * 128,
            p_wxlo + (size_t)l * DII * 128, p_part,
            BSS, 48, 128, DII, DII / 8, nullptr, nullptr, 0);

        coeff_kernel<<<BSS / 16, 256>>>(
            p_part, p_xn,
            dt_w + (size_t)l * DSS * DSS, dt_b + (size_t)l * DSS,
            a_log + (size_t)l * DSS, p_coeff);

        scan_kernel<<<BB * (DII / 16), 64>>>(
            p_xc, p_coeff, p_proj, d_param + (size_t)l * DII, p_yhi, p_ylo);

        // h += yg @ out_proj_w[l]   (M=2048, N=512, K=1024), K-split 4 + reduce
        gemm_f16<3><<<dim3(BSS / 128, DD / 128, 4), 256, 2 * ST3>>>(
            p_yhi, p_ylo, p_wohi + (size_t)l * DII * DD,
            p_wolo + (size_t)l * DII * DD, p_part,
            BSS, DD, DD, DII, DII / 4, nullptr, nullptr, 0);
        resid_add_kernel<<<(BSS * DD / 4) / 256, 256>>>(p_h, p_part, p_hhi, p_hlo);
    }

    // logits = h @ out_w + out_b  (M=2048, N=50257 pad 50432, K=512), TERMS=1
    gemm_f16<1><<<dim3(BSS / 128, NPADV / 128, 1), 256, 3 * ST1>>>(
        p_hhi, nullptr, p_bhi, nullptr, out, BSS, VV, NPADV, DD, DD,
        out_b, nullptr, 1);
}